// round 15
// baseline (speedup 1.0000x reference)
#include <cuda_runtime.h>
#include <cuda_fp16.h>
#include <cstdint>
#include <cstddef>

#define FC 32768
#define FFINE 131072
#define NCOL 3

typedef unsigned short u16;
typedef unsigned int   u32;
typedef unsigned long long u64;

// ----------------------------------------------------------------------------
// Device scratch (allocation-free rule)
// ----------------------------------------------------------------------------
__device__ int g_is64;
__device__ __align__(16) float g_s[352];                    // s0(128) s1(128) s2(96)
__device__ __align__(16) u16   g_W0h[3 * 128 * 128];        // [type][i=k][o=n] fp16
__device__ __align__(16) u16   g_W1h[3 * 128 * 96];
__device__ __align__(16) float g_wrgbs[NCOL * 96];
__device__ __align__(16) u16   g_x0s[(size_t)FC * 128];     // fp16 rows (256B)
__device__ __align__(16) u16   g_h1s[(size_t)FFINE * 128];
__device__ __align__(16) u16   g_hc16[(size_t)FC * 128];    // conv0 fp16 out
__device__ __align__(16) float g_imgpart[(size_t)FFINE * NCOL];

// ----------------------------------------------------------------------------
// Helpers
// ----------------------------------------------------------------------------
__device__ __forceinline__ u32 s2u(const void *p) {
    u32 a;
    asm("{ .reg .u64 t; cvta.to.shared.u64 t, %1; cvt.u32.u64 %0, t; }" : "=r"(a) : "l"(p));
    return a;
}
__device__ __forceinline__ float actf(float v, float b) {
    v += b;
    v = (v > 0.0f) ? v : 0.2f * v;
    v *= 1.41421356237309515f;
    return fminf(256.0f, fmaxf(-256.0f, v));
}
__device__ __forceinline__ int rdidx(const void *fn, size_t i, int is64) {
    return is64 ? (int)((const long long *)fn)[i] : ((const int *)fn)[i];
}
__device__ __forceinline__ void ldmx4(u32 addr, u32 *r) {
    asm volatile("ldmatrix.sync.aligned.m8n8.x4.shared.b16 {%0,%1,%2,%3}, [%4];"
                 : "=r"(r[0]), "=r"(r[1]), "=r"(r[2]), "=r"(r[3]) : "r"(addr));
}
__device__ __forceinline__ void ldmx4t(u32 addr, u32 *r) {
    asm volatile("ldmatrix.sync.aligned.m8n8.x4.trans.shared.b16 {%0,%1,%2,%3}, [%4];"
                 : "=r"(r[0]), "=r"(r[1]), "=r"(r[2]), "=r"(r[3]) : "r"(addr));
}
__device__ __forceinline__ void ldmx2t(u32 addr, u32 *r) {
    asm volatile("ldmatrix.sync.aligned.m8n8.x2.trans.shared.b16 {%0,%1}, [%2];"
                 : "=r"(r[0]), "=r"(r[1]) : "r"(addr));
}
__device__ __forceinline__ void mma16816(float *d, const u32 *a, const u32 *b) {
    asm volatile(
        "mma.sync.aligned.m16n8k16.row.col.f32.f16.f16.f32 "
        "{%0,%1,%2,%3}, {%4,%5,%6,%7}, {%8,%9}, {%0,%1,%2,%3};"
        : "+f"(d[0]), "+f"(d[1]), "+f"(d[2]), "+f"(d[3])
        : "r"(a[0]), "r"(a[1]), "r"(a[2]), "r"(a[3]), "r"(b[0]), "r"(b[1]));
}
__device__ __forceinline__ void cpa16(u32 d, const void *s, u32 sz) {
    asm volatile("cp.async.cg.shared.global [%0], [%1], 16, %2;"
                 :: "r"(d), "l"((u64)__cvta_generic_to_global(s)), "r"(sz) : "memory");
}
#define CPCOMMIT() asm volatile("cp.async.commit_group;" ::: "memory")
#define CPWAIT2()  asm volatile("cp.async.wait_group 2;" ::: "memory")

// ----------------------------------------------------------------------------
// Prep 1: styles, one warp per output row. Block 0/thread 0 also detects the
// index dtype (int64 values are small non-negative -> high words all zero).
// ----------------------------------------------------------------------------
__global__ void __launch_bounds__(128)
prep_styles_kernel(const void *__restrict__ fn1raw,
                   const float *__restrict__ ws,
                   const float *__restrict__ a0w, const float *__restrict__ a0b,
                   const float *__restrict__ a1w, const float *__restrict__ a1b,
                   const float *__restrict__ a2w, const float *__restrict__ a2b) {
    if (blockIdx.x == 0 && threadIdx.x == 0) {
        const unsigned *u = (const unsigned *)fn1raw;
        int all0 = 1;
        for (int t = 0; t < 64; t++)
            if (u[2 * t + 1] != 0u) { all0 = 0; break; }
        g_is64 = all0;
    }
    const float inv512 = 0.044194173824159216f;
    const float inv96  = 0.10206207261596575f;
    int gw = blockIdx.x * 4 + (threadIdx.x >> 5);
    int lane = threadIdx.x & 31;
    if (gw >= 352) return;
    const float *wrow, *v;
    float bv, post;
    if (gw < 128)      { wrow = a0w + gw * 512;          v = ws;        bv = a0b[gw];        post = 1.f; }
    else if (gw < 256) { wrow = a1w + (gw - 128) * 512;  v = ws + 512;  bv = a1b[gw - 128];  post = 1.f; }
    else               { wrow = a2w + (gw - 256) * 512;  v = ws + 1024; bv = a2b[gw - 256];  post = inv96; }
    float s = 0.f;
#pragma unroll
    for (int t = 0; t < 16; t++) {
        int d = lane + 32 * t;
        s += v[d] * wrow[d];
    }
#pragma unroll
    for (int o = 16; o > 0; o >>= 1) s += __shfl_xor_sync(0xffffffffu, s, o);
    if (lane == 0) g_s[gw] = (s * inv512 + bv) * post;
}

// ----------------------------------------------------------------------------
// Prep 2 (fused): blocks [0,224): demod + fp16 weight tables;
// blocks [224,...): pack conv0 input rows (fp16, 256B rows).
// ----------------------------------------------------------------------------
__global__ void __launch_bounds__(128)
prep_wp_kernel(const float *__restrict__ wc0, const float *__restrict__ ws0,
               const float *__restrict__ wr0,
               const float *__restrict__ wc1, const float *__restrict__ ws1,
               const float *__restrict__ wr1,
               const float *__restrict__ x, const float *__restrict__ sf,
               const float *__restrict__ wrgb) {
    __shared__ float red[4];
    __shared__ float dsh;
    int blk = blockIdx.x, tid = threadIdx.x;
    if (blk < 224) {
        const int isc0 = (blk < 128);
        const int o = isc0 ? blk : blk - 128;
        const int OUTC = isc0 ? 128 : 96;
        const float *pa = isc0 ? wc0 : wc1;
        const float *pb = isc0 ? ws0 : ws1;
        const float *pc = isc0 ? wr0 : wr1;
        u16 *dst = isc0 ? g_W0h : g_W1h;
        const float *sv = isc0 ? g_s : (g_s + 128);
        int i = tid;
        float a = pa[o * 128 + i], b = pb[o * 128 + i], c = pc[o * 128 + i];
        float si = sv[i];
        float part = si * si * (a * a + 4.f * b * b + 4.f * c * c);
#pragma unroll
        for (int off = 16; off > 0; off >>= 1)
            part += __shfl_xor_sync(0xffffffffu, part, off);
        if ((tid & 31) == 0) red[tid >> 5] = part;
        __syncthreads();
        if (tid == 0) dsh = 1.0f / sqrtf(red[0] + red[1] + red[2] + red[3] + 1e-8f);
        __syncthreads();
        float sid = si * dsh;
        dst[((size_t)0 * 128 + i) * OUTC + o] = __half_as_ushort(__float2half_rn(a * sid));
        dst[((size_t)1 * 128 + i) * OUTC + o] = __half_as_ushort(__float2half_rn(b * sid));
        dst[((size_t)2 * 128 + i) * OUTC + o] = __half_as_ushort(__float2half_rn(c * sid));
        if (!isc0 && tid < 3)
            g_wrgbs[tid * 96 + o] = wrgb[tid * 96 + o] * g_s[256 + o];
    } else {
        int face = (blk - 224) * 4 + (tid >> 5);
        int lane = tid & 31, c = lane * 4;
        float4 v;
        if (c < 96) v = __ldg((const float4 *)(x + (size_t)face * 96) + lane);
        else        v = __ldg((const float4 *)(sf + (size_t)face * 32) + (lane - 24));
        ushort4 h;
        h.x = __half_as_ushort(__float2half_rn(v.x));
        h.y = __half_as_ushort(__float2half_rn(v.y));
        h.z = __half_as_ushort(__float2half_rn(v.z));
        h.w = __half_as_ushort(__float2half_rn(v.w));
        *(ushort4 *)&g_x0s[(size_t)face * 128 + c] = h;
    }
}

// ----------------------------------------------------------------------------
// A staging: 128 rows x 256B (16 x 16B chunks), chunk j at r*256 + ((j^(r&7))<<4).
// 512 threads, 4 chunks each. fn read raw (is64-aware).
// ----------------------------------------------------------------------------
__device__ __forceinline__ void stageA_f(u32 Ad, const u16 *tbl, const void *fn,
                                         int fbase, int k, int tid, int NF, int is64) {
    int r = tid >> 2, q = tid & 3;
    int idx = rdidx(fn, (size_t)(fbase + r) * 9 + k, is64);
    u32 sz = (idx < NF) ? 16u : 0u;
    const char *src = (const char *)tbl + (size_t)(idx < NF ? idx : 0) * 256;
    u32 drow = Ad + (u32)r * 256;
    u32 x = (u32)(r & 7) << 4;
#pragma unroll
    for (int j = q * 4; j < q * 4 + 4; j++)
        cpa16(drow + (((u32)j << 4) ^ x), src + j * 16, sz);
}
// B staging (once): 3 types x 128 rows, row stride 256B (conv1 rows padded).
template <int OUTC>
__device__ __forceinline__ void stageB_all(u32 Bs, const u16 *Wg, int tid) {
    constexpr int NCH = OUTC / 8;  // 16B chunks per row
    for (int cid = tid; cid < 3 * 128 * NCH; cid += 512) {
        int type = cid / (128 * NCH);
        int rr = (cid / NCH) % 128;
        int j = cid % NCH;
        u32 dst = Bs + (u32)type * 32768u + (u32)rr * 256u + (((u32)j << 4) ^ ((u32)(rr & 7) << 4));
        const char *src = (const char *)Wg + ((size_t)type * 128 + rr) * OUTC * 2 + j * 16;
        cpa16(dst, src, 16u);
    }
}

// ----------------------------------------------------------------------------
// HMMA face conv + max over 9 positions, 1-pass fp16, interleaved inner loop
// (both m-subtiles in flight; B ldmatrix per k-step — measured-best form).
// 512 threads: 4 m-warps (32 rows) x 4 n-quarters (OUTC/4 cols).
// ----------------------------------------------------------------------------
template <int WHICH>
__global__ void __launch_bounds__(512, 1)
convmma_kernel(const void *__restrict__ fn,
               const float *__restrict__ nc, const float *__restrict__ nsp,
               const float *__restrict__ bias, float *__restrict__ outp) {
    constexpr int OUTC = (WHICH == 0) ? 128 : 96;
    constexpr int NF = (WHICH == 0) ? FC : FFINE;
    constexpr int NT = NF / 128;
    constexpr int NTL = (WHICH == 0) ? 4 : 3;  // n-tiles (8 cols) per warp

    extern __shared__ char sm[];
    const u32 As = s2u(sm);            // 4 x 32KB ring
    const u32 Bs = As + 131072u;       // 3 x 32KB types
    const u16 *tbl = (WHICH == 0) ? g_x0s : g_h1s;
    const u16 *Wg  = (WHICH == 0) ? g_W0h : g_W1h;
    const int is64 = g_is64;

    const int tid = threadIdx.x, lane = tid & 31, w = tid >> 5;
    const int wm = w & 3, wq = w >> 2;
    const int lrow = lane & 15, lsc = lane >> 4;
    const u32 ax = (u32)(lrow & 7) << 4;
    const int nbase = wq * NTL;
    u32 aoff[2];
#pragma unroll
    for (int ms = 0; ms < 2; ms++) aoff[ms] = (u32)(wm * 32 + ms * 16 + lrow) * 256u;
    const float nsv = (WHICH == 1) ? __ldg(nsp) : 0.f;
    float breg[NTL][2];
    if (WHICH == 1) {
#pragma unroll
        for (int n = 0; n < NTL; n++) {
            int o = nbase * 8 + n * 8 + (lane & 3) * 2;
            breg[n][0] = __ldg(&bias[o]);
            breg[n][1] = __ldg(&bias[o + 1]);
        }
    }

    const int bid = blockIdx.x, grid = gridDim.x;
    const int ntile = (NT - bid + grid - 1) / grid;
    const int steps = ntile * 9;

    // prologue: B (all types) + A(0) in group0; A(1) in group1
    stageB_all<OUTC>(Bs, Wg, tid);
    if (steps > 0) stageA_f(As, tbl, fn, bid * 128, 0, tid, NF, is64);
    CPCOMMIT();
    if (steps > 1) stageA_f(As + 32768u, tbl, fn, bid * 128, 1, tid, NF, is64);
    CPCOMMIT();

    float mx[2][NTL][4];

    for (int s = 0; s < steps; s++) {
        const int k = s - (s / 9) * 9;
        // stage A(s+2)
        {
            int u = s + 2;
            if (u < steps) {
                int ut = u / 9;
                stageA_f(As + (u32)(u & 3) * 32768u, tbl, fn,
                         (bid + ut * grid) * 128, u - ut * 9, tid, NF, is64);
            }
        }
        CPCOMMIT();
        CPWAIT2();
        __syncthreads();

        if (k == 0) {
#pragma unroll
            for (int ms = 0; ms < 2; ms++)
#pragma unroll
                for (int n = 0; n < NTL; n++)
#pragma unroll
                    for (int q = 0; q < 4; q++) mx[ms][n][q] = -3.4e38f;
        }

        const u32 Acur = As + (u32)(s & 3) * 32768u;
        const u32 Bt = Bs + (u32)((k == 0) ? 0 : (k < 5 ? 1 : 2)) * 32768u;
        float acc[2][NTL][4];
#pragma unroll
        for (int ms = 0; ms < 2; ms++)
#pragma unroll
            for (int n = 0; n < NTL; n++)
#pragma unroll
                for (int q = 0; q < 4; q++) acc[ms][n][q] = 0.f;

#pragma unroll
        for (int c = 0; c < 8; c++) {
            u32 a[2][4], bf[NTL][2];
#pragma unroll
            for (int ms = 0; ms < 2; ms++)
                ldmx4(Acur + aoff[ms] + (((u32)(2 * c + lsc) << 4) ^ ax), a[ms]);
            const u32 brow = Bt + (u32)(16 * c + lrow) * 256u;
            if (WHICH == 0) {
#pragma unroll
                for (int p = 0; p < 2; p++) {
                    u32 r4[4];
                    ldmx4t(brow + (((u32)(nbase + 2 * p + lsc) << 4) ^ ax), r4);
                    bf[2 * p][0] = r4[0]; bf[2 * p][1] = r4[1];
                    bf[2 * p + 1][0] = r4[2]; bf[2 * p + 1][1] = r4[3];
                }
            } else {
                u32 r4[4];
                ldmx4t(brow + (((u32)(nbase + lsc) << 4) ^ ax), r4);
                bf[0][0] = r4[0]; bf[0][1] = r4[1];
                bf[1][0] = r4[2]; bf[1][1] = r4[3];
                u32 r2[2];
                ldmx2t(brow + (((u32)(nbase + 2) << 4) ^ ax), r2);
                bf[2][0] = r2[0]; bf[2][1] = r2[1];
            }
#pragma unroll
            for (int ms = 0; ms < 2; ms++)
#pragma unroll
                for (int n = 0; n < NTL; n++) mma16816(acc[ms][n], a[ms], bf[n]);
        }
#pragma unroll
        for (int ms = 0; ms < 2; ms++)
#pragma unroll
            for (int n = 0; n < NTL; n++)
#pragma unroll
                for (int q = 0; q < 4; q++)
                    mx[ms][n][q] = fmaxf(mx[ms][n][q], acc[ms][n][q]);

        if (k == 8) {
            const int fbase = (bid + (s / 9) * grid) * 128;
#pragma unroll
            for (int ms = 0; ms < 2; ms++) {
                int f0 = fbase + wm * 32 + ms * 16 + (lane >> 2);
                if (WHICH == 0) {
#pragma unroll
                    for (int n = 0; n < NTL; n++) {
                        int o = nbase * 8 + n * 8 + (lane & 3) * 2;
                        __half2 h01 = __floats2half2_rn(mx[ms][n][0], mx[ms][n][1]);
                        __half2 h23 = __floats2half2_rn(mx[ms][n][2], mx[ms][n][3]);
                        *(u32 *)&g_hc16[(size_t)f0 * 128 + o] = *reinterpret_cast<u32 *>(&h01);
                        *(u32 *)&g_hc16[(size_t)(f0 + 8) * 128 + o] = *reinterpret_cast<u32 *>(&h23);
                    }
                } else {
                    float nz0 = __ldg(&nc[f0]) * nsv;
                    float nz1 = __ldg(&nc[f0 + 8]) * nsv;
#pragma unroll
                    for (int n = 0; n < NTL; n++) {
                        int o = nbase * 8 + n * 8 + (lane & 3) * 2;
                        *(float2 *)&outp[(size_t)f0 * 96 + o] =
                            make_float2(actf(mx[ms][n][0] + nz0, breg[n][0]),
                                        actf(mx[ms][n][1] + nz0, breg[n][1]));
                        *(float2 *)&outp[(size_t)(f0 + 8) * 96 + o] =
                            make_float2(actf(mx[ms][n][2] + nz1, breg[n][0]),
                                        actf(mx[ms][n][3] + nz1, breg[n][1]));
                    }
                }
            }
        }
    }
}

// ----------------------------------------------------------------------------
// Smooth upsample: packed half2 accumulation in 3 rotating slots (<=3 adds per
// fp16 chain), fp32 combine in epilogue. No dedup (indices ~collision-free).
// ----------------------------------------------------------------------------
__global__ void __launch_bounds__(256) upsample_kernel(const void *__restrict__ fn1,
                                                       const void *__restrict__ pm,
                                                       const float *__restrict__ img,
                                                       const float *__restrict__ nc0,
                                                       const float *__restrict__ ns0,
                                                       const float *__restrict__ bias0) {
    const int warp = threadIdx.x >> 5, lane = threadIdx.x & 31;
    const int face = blockIdx.x * 8 + warp;
    const int is64 = g_is64;
    int myrow = -1;
    if (lane < 9) {
        int v = rdidx(fn1, (size_t)face * 9 + lane, is64);
        myrow = (v < FFINE) ? rdidx(pm, v, is64) : -1;
    }
    __half2 a01[3], a23[3];
#pragma unroll
    for (int t = 0; t < 3; t++) {
        a01[t] = __floats2half2_rn(0.f, 0.f);
        a23[t] = __floats2half2_rn(0.f, 0.f);
    }
    float simg = 0.f;
#pragma unroll
    for (int k = 0; k < 9; k++) {
        int rk = __shfl_sync(0xffffffffu, myrow, k);
        if (rk >= 0) {
            uint2 raw = __ldg((const uint2 *)(g_hc16 + (size_t)rk * 128) + lane);
            a01[k % 3] = __hadd2(a01[k % 3], *reinterpret_cast<__half2 *>(&raw.x));
            a23[k % 3] = __hadd2(a23[k % 3], *reinterpret_cast<__half2 *>(&raw.y));
            if (lane < 3) simg += img[rk * 3 + lane];
        }
    }
    float4 a;
    a.x = __low2float(a01[0]) + __low2float(a01[1]) + __low2float(a01[2]);
    a.y = __high2float(a01[0]) + __high2float(a01[1]) + __high2float(a01[2]);
    a.z = __low2float(a23[0]) + __low2float(a23[1]) + __low2float(a23[2]);
    a.w = __high2float(a23[0]) + __high2float(a23[1]) + __high2float(a23[2]);

    const float inv9 = 1.0f / 9.0f;
    float noise = nc0[face] * ns0[0];
    int c = lane * 4;
    float4 b = *(const float4 *)&bias0[c];
    ushort4 h;
    h.x = __half_as_ushort(__float2half_rn(actf(a.x * inv9 + noise, b.x)));
    h.y = __half_as_ushort(__float2half_rn(actf(a.y * inv9 + noise, b.y)));
    h.z = __half_as_ushort(__float2half_rn(actf(a.z * inv9 + noise, b.z)));
    h.w = __half_as_ushort(__float2half_rn(actf(a.w * inv9 + noise, b.w)));
    *(ushort4 *)&g_h1s[(size_t)face * 128 + c] = h;

    if (lane < 3) g_imgpart[(size_t)face * 3 + lane] = simg * inv9;
}

// ----------------------------------------------------------------------------
// toRGB
// ----------------------------------------------------------------------------
__global__ void __launch_bounds__(256) torgb_kernel(const void *__restrict__ fn1,
                                                    const float *__restrict__ brgb,
                                                    float *__restrict__ dout) {
    const float *hout = dout;
    float *imgout = dout + (size_t)FFINE * 96;
    const int warp = threadIdx.x >> 5, lane = threadIdx.x & 31;
    const int face = blockIdx.x * 8 + warp;
    int idx = rdidx(fn1, (size_t)face * 9, g_is64);
    float x0 = 0.f, x1 = 0.f, x2 = 0.f;
    if (idx < FFINE) {
        const float *hr = hout + (size_t)idx * 96;
        x0 = hr[lane]; x1 = hr[lane + 32]; x2 = hr[lane + 64];
    }
#pragma unroll
    for (int o = 0; o < 3; o++) {
        float p = x0 * g_wrgbs[o * 96 + lane] + x1 * g_wrgbs[o * 96 + lane + 32] +
                  x2 * g_wrgbs[o * 96 + lane + 64];
#pragma unroll
        for (int s = 16; s > 0; s >>= 1) p += __shfl_xor_sync(0xffffffffu, p, s);
        if (lane == 0) {
            float y = p + brgb[o];
            y = fminf(256.0f, fmaxf(-256.0f, y));
            imgout[(size_t)face * 3 + o] = g_imgpart[(size_t)face * 3 + o] + y;
        }
    }
}

// ----------------------------------------------------------------------------
// Host launcher
// ----------------------------------------------------------------------------
extern "C" void kernel_launch(void *const *d_in, const int *in_sizes, int n_in,
                              void *d_out, int out_size) {
    int base = n_in - 20;

    const float *x   = (const float *)d_in[0];
    const float *sf  = (const float *)d_in[1];
    const float *img = (const float *)d_in[2];
    const float *ws  = (const float *)d_in[3];
    const void  *fn0 = d_in[4];
    const void  *fn1 = d_in[5];
    const void  *pm  = d_in[6];

    const float *a0w  = (const float *)d_in[base + 0];
    const float *a0b  = (const float *)d_in[base + 1];
    const float *wc0  = (const float *)d_in[base + 2];
    const float *ws0  = (const float *)d_in[base + 3];
    const float *wr0  = (const float *)d_in[base + 4];
    const float *ns0  = (const float *)d_in[base + 5];
    const float *b0   = (const float *)d_in[base + 6];
    const float *nc0  = (const float *)d_in[base + 7];
    const float *a1w  = (const float *)d_in[base + 8];
    const float *a1b  = (const float *)d_in[base + 9];
    const float *wc1  = (const float *)d_in[base + 10];
    const float *ws1  = (const float *)d_in[base + 11];
    const float *wr1  = (const float *)d_in[base + 12];
    const float *ns1  = (const float *)d_in[base + 13];
    const float *b1   = (const float *)d_in[base + 14];
    const float *nc1  = (const float *)d_in[base + 15];
    const float *a2w  = (const float *)d_in[base + 16];
    const float *a2b  = (const float *)d_in[base + 17];
    const float *wrgb = (const float *)d_in[base + 18];
    const float *brgb = (const float *)d_in[base + 19];

    const int SMEM = 4 * 32768 + 3 * 32768;  // 229376 (A ring + 3 B types)
    cudaFuncSetAttribute(convmma_kernel<0>, cudaFuncAttributeMaxDynamicSharedMemorySize, SMEM);
    cudaFuncSetAttribute(convmma_kernel<1>, cudaFuncAttributeMaxDynamicSharedMemorySize, SMEM);

    int sms = 148;
    cudaDeviceGetAttribute(&sms, cudaDevAttrMultiProcessorCount, 0);

    float *out = (float *)d_out;
    prep_styles_kernel<<<88, 128>>>(fn1, ws, a0w, a0b, a1w, a1b, a2w, a2b);     // 0
    prep_wp_kernel<<<224 + FC / 4, 128>>>(wc0, ws0, wr0, wc1, ws1, wr1,
                                          x, sf, wrgb);                         // 1
    convmma_kernel<0><<<128, 512, SMEM>>>(fn0, nc0, ns0, b0, out);              // 2
    upsample_kernel<<<FFINE / 8, 256>>>(fn1, pm, img, nc0, ns0, b0);            // 3 (captured)
    convmma_kernel<1><<<sms, 512, SMEM>>>(fn1, nc1, ns1, b1, out);              // 4

    if (out_size >= (long long)FFINE * (96 + NCOL))
        torgb_kernel<<<FFINE / 8, 256>>>(fn1, brgb, out);                       // 5
}

// round 16
// speedup vs baseline: 1.0864x; 1.0864x over previous
#include <cuda_runtime.h>
#include <cuda_fp16.h>
#include <cstdint>
#include <cstddef>

#define FC 32768
#define FFINE 131072
#define NCOL 3

typedef unsigned short u16;
typedef unsigned int   u32;
typedef unsigned long long u64;

// ----------------------------------------------------------------------------
// Device scratch (allocation-free rule)
// ----------------------------------------------------------------------------
__device__ int g_is64;
__device__ __align__(16) float g_s[352];                    // s0(128) s1(128) s2(96)
__device__ __align__(16) u16   g_W0h[3 * 128 * 128];        // [type][i=k][o=n] fp16
__device__ __align__(16) u16   g_W1h[3 * 128 * 96];
__device__ __align__(16) float g_wrgbs[NCOL * 96];
__device__ __align__(16) u16   g_x0s[(size_t)FC * 128];     // fp16 rows (256B)
__device__ __align__(16) u16   g_h1s[(size_t)FFINE * 128];
__device__ __align__(16) u16   g_hc16[((size_t)FC + 8) * 128];  // conv0 fp16 out (+zero row FC)
__device__ __align__(16) float g_imgpart[(size_t)FFINE * NCOL];

// ----------------------------------------------------------------------------
// Helpers
// ----------------------------------------------------------------------------
__device__ __forceinline__ u32 s2u(const void *p) {
    u32 a;
    asm("{ .reg .u64 t; cvta.to.shared.u64 t, %1; cvt.u32.u64 %0, t; }" : "=r"(a) : "l"(p));
    return a;
}
__device__ __forceinline__ float actf(float v, float b) {
    v += b;
    v = (v > 0.0f) ? v : 0.2f * v;
    v *= 1.41421356237309515f;
    return fminf(256.0f, fmaxf(-256.0f, v));
}
__device__ __forceinline__ int rdidx(const void *fn, size_t i, int is64) {
    return is64 ? (int)((const long long *)fn)[i] : ((const int *)fn)[i];
}
__device__ __forceinline__ void ldmx4(u32 addr, u32 *r) {
    asm volatile("ldmatrix.sync.aligned.m8n8.x4.shared.b16 {%0,%1,%2,%3}, [%4];"
                 : "=r"(r[0]), "=r"(r[1]), "=r"(r[2]), "=r"(r[3]) : "r"(addr));
}
__device__ __forceinline__ void ldmx4t(u32 addr, u32 *r) {
    asm volatile("ldmatrix.sync.aligned.m8n8.x4.trans.shared.b16 {%0,%1,%2,%3}, [%4];"
                 : "=r"(r[0]), "=r"(r[1]), "=r"(r[2]), "=r"(r[3]) : "r"(addr));
}
__device__ __forceinline__ void ldmx2t(u32 addr, u32 *r) {
    asm volatile("ldmatrix.sync.aligned.m8n8.x2.trans.shared.b16 {%0,%1}, [%2];"
                 : "=r"(r[0]), "=r"(r[1]) : "r"(addr));
}
__device__ __forceinline__ void mma16816(float *d, const u32 *a, const u32 *b) {
    asm volatile(
        "mma.sync.aligned.m16n8k16.row.col.f32.f16.f16.f32 "
        "{%0,%1,%2,%3}, {%4,%5,%6,%7}, {%8,%9}, {%0,%1,%2,%3};"
        : "+f"(d[0]), "+f"(d[1]), "+f"(d[2]), "+f"(d[3])
        : "r"(a[0]), "r"(a[1]), "r"(a[2]), "r"(a[3]), "r"(b[0]), "r"(b[1]));
}
__device__ __forceinline__ void cpa16(u32 d, const void *s, u32 sz) {
    asm volatile("cp.async.cg.shared.global [%0], [%1], 16, %2;"
                 :: "r"(d), "l"((u64)__cvta_generic_to_global(s)), "r"(sz) : "memory");
}
#define CPCOMMIT() asm volatile("cp.async.commit_group;" ::: "memory")
#define CPWAIT2()  asm volatile("cp.async.wait_group 2;" ::: "memory")

// ----------------------------------------------------------------------------
// Prep 1: styles, one warp per output row. Block 0/thread 0 also detects the
// index dtype (int64 values are small non-negative -> high words all zero).
// ----------------------------------------------------------------------------
__global__ void __launch_bounds__(128)
prep_styles_kernel(const void *__restrict__ fn1raw,
                   const float *__restrict__ ws,
                   const float *__restrict__ a0w, const float *__restrict__ a0b,
                   const float *__restrict__ a1w, const float *__restrict__ a1b,
                   const float *__restrict__ a2w, const float *__restrict__ a2b) {
    if (blockIdx.x == 0 && threadIdx.x == 0) {
        const unsigned *u = (const unsigned *)fn1raw;
        int all0 = 1;
        for (int t = 0; t < 64; t++)
            if (u[2 * t + 1] != 0u) { all0 = 0; break; }
        g_is64 = all0;
    }
    const float inv512 = 0.044194173824159216f;
    const float inv96  = 0.10206207261596575f;
    int gw = blockIdx.x * 4 + (threadIdx.x >> 5);
    int lane = threadIdx.x & 31;
    if (gw >= 352) return;
    const float *wrow, *v;
    float bv, post;
    if (gw < 128)      { wrow = a0w + gw * 512;          v = ws;        bv = a0b[gw];        post = 1.f; }
    else if (gw < 256) { wrow = a1w + (gw - 128) * 512;  v = ws + 512;  bv = a1b[gw - 128];  post = 1.f; }
    else               { wrow = a2w + (gw - 256) * 512;  v = ws + 1024; bv = a2b[gw - 256];  post = inv96; }
    float s = 0.f;
#pragma unroll
    for (int t = 0; t < 16; t++) {
        int d = lane + 32 * t;
        s += v[d] * wrow[d];
    }
#pragma unroll
    for (int o = 16; o > 0; o >>= 1) s += __shfl_xor_sync(0xffffffffu, s, o);
    if (lane == 0) g_s[gw] = (s * inv512 + bv) * post;
}

// ----------------------------------------------------------------------------
// Prep 2 (fused): blocks [0,224): demod + fp16 weight tables;
// blocks [224,...): pack conv0 input rows (fp16, 256B rows).
// ----------------------------------------------------------------------------
__global__ void __launch_bounds__(128)
prep_wp_kernel(const float *__restrict__ wc0, const float *__restrict__ ws0,
               const float *__restrict__ wr0,
               const float *__restrict__ wc1, const float *__restrict__ ws1,
               const float *__restrict__ wr1,
               const float *__restrict__ x, const float *__restrict__ sf,
               const float *__restrict__ wrgb) {
    __shared__ float red[4];
    __shared__ float dsh;
    int blk = blockIdx.x, tid = threadIdx.x;
    if (blk < 224) {
        const int isc0 = (blk < 128);
        const int o = isc0 ? blk : blk - 128;
        const int OUTC = isc0 ? 128 : 96;
        const float *pa = isc0 ? wc0 : wc1;
        const float *pb = isc0 ? ws0 : ws1;
        const float *pc = isc0 ? wr0 : wr1;
        u16 *dst = isc0 ? g_W0h : g_W1h;
        const float *sv = isc0 ? g_s : (g_s + 128);
        int i = tid;
        float a = pa[o * 128 + i], b = pb[o * 128 + i], c = pc[o * 128 + i];
        float si = sv[i];
        float part = si * si * (a * a + 4.f * b * b + 4.f * c * c);
#pragma unroll
        for (int off = 16; off > 0; off >>= 1)
            part += __shfl_xor_sync(0xffffffffu, part, off);
        if ((tid & 31) == 0) red[tid >> 5] = part;
        __syncthreads();
        if (tid == 0) dsh = 1.0f / sqrtf(red[0] + red[1] + red[2] + red[3] + 1e-8f);
        __syncthreads();
        float sid = si * dsh;
        dst[((size_t)0 * 128 + i) * OUTC + o] = __half_as_ushort(__float2half_rn(a * sid));
        dst[((size_t)1 * 128 + i) * OUTC + o] = __half_as_ushort(__float2half_rn(b * sid));
        dst[((size_t)2 * 128 + i) * OUTC + o] = __half_as_ushort(__float2half_rn(c * sid));
        if (!isc0 && tid < 3)
            g_wrgbs[tid * 96 + o] = wrgb[tid * 96 + o] * g_s[256 + o];
    } else {
        int face = (blk - 224) * 4 + (tid >> 5);
        int lane = tid & 31, c = lane * 4;
        float4 v;
        if (c < 96) v = __ldg((const float4 *)(x + (size_t)face * 96) + lane);
        else        v = __ldg((const float4 *)(sf + (size_t)face * 32) + (lane - 24));
        ushort4 h;
        h.x = __half_as_ushort(__float2half_rn(v.x));
        h.y = __half_as_ushort(__float2half_rn(v.y));
        h.z = __half_as_ushort(__float2half_rn(v.z));
        h.w = __half_as_ushort(__float2half_rn(v.w));
        *(ushort4 *)&g_x0s[(size_t)face * 128 + c] = h;
    }
}

// ----------------------------------------------------------------------------
// A staging: 128 rows x 256B (16 x 16B chunks), chunk j at r*256 + ((j^(r&7))<<4).
// 512 threads, 4 chunks each. fn read raw (is64-aware).
// ----------------------------------------------------------------------------
__device__ __forceinline__ void stageA_f(u32 Ad, const u16 *tbl, const void *fn,
                                         int fbase, int k, int tid, int NF, int is64) {
    int r = tid >> 2, q = tid & 3;
    int idx = rdidx(fn, (size_t)(fbase + r) * 9 + k, is64);
    u32 sz = (idx < NF) ? 16u : 0u;
    const char *src = (const char *)tbl + (size_t)(idx < NF ? idx : 0) * 256;
    u32 drow = Ad + (u32)r * 256;
    u32 x = (u32)(r & 7) << 4;
#pragma unroll
    for (int j = q * 4; j < q * 4 + 4; j++)
        cpa16(drow + (((u32)j << 4) ^ x), src + j * 16, sz);
}
// B staging (once): 3 types x 128 rows, row stride 256B (conv1 rows padded).
template <int OUTC>
__device__ __forceinline__ void stageB_all(u32 Bs, const u16 *Wg, int tid) {
    constexpr int NCH = OUTC / 8;  // 16B chunks per row
    for (int cid = tid; cid < 3 * 128 * NCH; cid += 512) {
        int type = cid / (128 * NCH);
        int rr = (cid / NCH) % 128;
        int j = cid % NCH;
        u32 dst = Bs + (u32)type * 32768u + (u32)rr * 256u + (((u32)j << 4) ^ ((u32)(rr & 7) << 4));
        const char *src = (const char *)Wg + ((size_t)type * 128 + rr) * OUTC * 2 + j * 16;
        cpa16(dst, src, 16u);
    }
}

// ----------------------------------------------------------------------------
// HMMA face conv + max over 9 positions, 1-pass fp16, interleaved inner loop
// (both m-subtiles in flight; B ldmatrix per k-step — measured-best form).
// 512 threads: 4 m-warps (32 rows) x 4 n-quarters (OUTC/4 cols).
// ----------------------------------------------------------------------------
template <int WHICH>
__global__ void __launch_bounds__(512, 1)
convmma_kernel(const void *__restrict__ fn,
               const float *__restrict__ nc, const float *__restrict__ nsp,
               const float *__restrict__ bias, float *__restrict__ outp) {
    constexpr int OUTC = (WHICH == 0) ? 128 : 96;
    constexpr int NF = (WHICH == 0) ? FC : FFINE;
    constexpr int NT = NF / 128;
    constexpr int NTL = (WHICH == 0) ? 4 : 3;  // n-tiles (8 cols) per warp

    extern __shared__ char sm[];
    const u32 As = s2u(sm);            // 4 x 32KB ring
    const u32 Bs = As + 131072u;       // 3 x 32KB types
    const u16 *tbl = (WHICH == 0) ? g_x0s : g_h1s;
    const u16 *Wg  = (WHICH == 0) ? g_W0h : g_W1h;
    const int is64 = g_is64;

    const int tid = threadIdx.x, lane = tid & 31, w = tid >> 5;
    const int wm = w & 3, wq = w >> 2;
    const int lrow = lane & 15, lsc = lane >> 4;
    const u32 ax = (u32)(lrow & 7) << 4;
    const int nbase = wq * NTL;
    u32 aoff[2];
#pragma unroll
    for (int ms = 0; ms < 2; ms++) aoff[ms] = (u32)(wm * 32 + ms * 16 + lrow) * 256u;
    const float nsv = (WHICH == 1) ? __ldg(nsp) : 0.f;
    float breg[NTL][2];
    if (WHICH == 1) {
#pragma unroll
        for (int n = 0; n < NTL; n++) {
            int o = nbase * 8 + n * 8 + (lane & 3) * 2;
            breg[n][0] = __ldg(&bias[o]);
            breg[n][1] = __ldg(&bias[o + 1]);
        }
    }

    const int bid = blockIdx.x, grid = gridDim.x;
    const int ntile = (NT - bid + grid - 1) / grid;
    const int steps = ntile * 9;

    // prologue: B (all types) + A(0) in group0; A(1) in group1
    stageB_all<OUTC>(Bs, Wg, tid);
    if (steps > 0) stageA_f(As, tbl, fn, bid * 128, 0, tid, NF, is64);
    CPCOMMIT();
    if (steps > 1) stageA_f(As + 32768u, tbl, fn, bid * 128, 1, tid, NF, is64);
    CPCOMMIT();

    float mx[2][NTL][4];

    for (int s = 0; s < steps; s++) {
        const int k = s - (s / 9) * 9;
        // stage A(s+2)
        {
            int u = s + 2;
            if (u < steps) {
                int ut = u / 9;
                stageA_f(As + (u32)(u & 3) * 32768u, tbl, fn,
                         (bid + ut * grid) * 128, u - ut * 9, tid, NF, is64);
            }
        }
        CPCOMMIT();
        CPWAIT2();
        __syncthreads();

        if (k == 0) {
#pragma unroll
            for (int ms = 0; ms < 2; ms++)
#pragma unroll
                for (int n = 0; n < NTL; n++)
#pragma unroll
                    for (int q = 0; q < 4; q++) mx[ms][n][q] = -3.4e38f;
        }

        const u32 Acur = As + (u32)(s & 3) * 32768u;
        const u32 Bt = Bs + (u32)((k == 0) ? 0 : (k < 5 ? 1 : 2)) * 32768u;
        float acc[2][NTL][4];
#pragma unroll
        for (int ms = 0; ms < 2; ms++)
#pragma unroll
            for (int n = 0; n < NTL; n++)
#pragma unroll
                for (int q = 0; q < 4; q++) acc[ms][n][q] = 0.f;

#pragma unroll
        for (int c = 0; c < 8; c++) {
            u32 a[2][4], bf[NTL][2];
#pragma unroll
            for (int ms = 0; ms < 2; ms++)
                ldmx4(Acur + aoff[ms] + (((u32)(2 * c + lsc) << 4) ^ ax), a[ms]);
            const u32 brow = Bt + (u32)(16 * c + lrow) * 256u;
            if (WHICH == 0) {
#pragma unroll
                for (int p = 0; p < 2; p++) {
                    u32 r4[4];
                    ldmx4t(brow + (((u32)(nbase + 2 * p + lsc) << 4) ^ ax), r4);
                    bf[2 * p][0] = r4[0]; bf[2 * p][1] = r4[1];
                    bf[2 * p + 1][0] = r4[2]; bf[2 * p + 1][1] = r4[3];
                }
            } else {
                u32 r4[4];
                ldmx4t(brow + (((u32)(nbase + lsc) << 4) ^ ax), r4);
                bf[0][0] = r4[0]; bf[0][1] = r4[1];
                bf[1][0] = r4[2]; bf[1][1] = r4[3];
                u32 r2[2];
                ldmx2t(brow + (((u32)(nbase + 2) << 4) ^ ax), r2);
                bf[2][0] = r2[0]; bf[2][1] = r2[1];
            }
#pragma unroll
            for (int ms = 0; ms < 2; ms++)
#pragma unroll
                for (int n = 0; n < NTL; n++) mma16816(acc[ms][n], a[ms], bf[n]);
        }
#pragma unroll
        for (int ms = 0; ms < 2; ms++)
#pragma unroll
            for (int n = 0; n < NTL; n++)
#pragma unroll
                for (int q = 0; q < 4; q++)
                    mx[ms][n][q] = fmaxf(mx[ms][n][q], acc[ms][n][q]);

        if (k == 8) {
            const int fbase = (bid + (s / 9) * grid) * 128;
#pragma unroll
            for (int ms = 0; ms < 2; ms++) {
                int f0 = fbase + wm * 32 + ms * 16 + (lane >> 2);
                if (WHICH == 0) {
#pragma unroll
                    for (int n = 0; n < NTL; n++) {
                        int o = nbase * 8 + n * 8 + (lane & 3) * 2;
                        __half2 h01 = __floats2half2_rn(mx[ms][n][0], mx[ms][n][1]);
                        __half2 h23 = __floats2half2_rn(mx[ms][n][2], mx[ms][n][3]);
                        *(u32 *)&g_hc16[(size_t)f0 * 128 + o] = *reinterpret_cast<u32 *>(&h01);
                        *(u32 *)&g_hc16[(size_t)(f0 + 8) * 128 + o] = *reinterpret_cast<u32 *>(&h23);
                    }
                } else {
                    float nz0 = __ldg(&nc[f0]) * nsv;
                    float nz1 = __ldg(&nc[f0 + 8]) * nsv;
#pragma unroll
                    for (int n = 0; n < NTL; n++) {
                        int o = nbase * 8 + n * 8 + (lane & 3) * 2;
                        *(float2 *)&outp[(size_t)f0 * 96 + o] =
                            make_float2(actf(mx[ms][n][0] + nz0, breg[n][0]),
                                        actf(mx[ms][n][1] + nz0, breg[n][1]));
                        *(float2 *)&outp[(size_t)(f0 + 8) * 96 + o] =
                            make_float2(actf(mx[ms][n][2] + nz1, breg[n][0]),
                                        actf(mx[ms][n][3] + nz1, breg[n][1]));
                    }
                }
            }
        }
    }
}

// ----------------------------------------------------------------------------
// Smooth upsample: 2 faces per warp (16 lanes x 8 channels, uint4 loads),
// fp32 accumulation, branch-free gather via zero row at index FC.
// ----------------------------------------------------------------------------
__global__ void __launch_bounds__(256) upsample_kernel(const void *__restrict__ fn1,
                                                       const void *__restrict__ pm,
                                                       const float *__restrict__ img,
                                                       const float *__restrict__ nc0,
                                                       const float *__restrict__ ns0,
                                                       const float *__restrict__ bias0) {
    const int warp = threadIdx.x >> 5, lane = threadIdx.x & 31;
    const int half = lane >> 4, hl = lane & 15;
    const int face = blockIdx.x * 16 + warp * 2 + half;
    const int is64 = g_is64;
    int myrow = FC;  // zero row
    if (hl < 9) {
        int v = rdidx(fn1, (size_t)face * 9 + hl, is64);
        if (v < FFINE) myrow = rdidx(pm, v, is64);
    }
    float acc[8];
#pragma unroll
    for (int j = 0; j < 8; j++) acc[j] = 0.f;
    float simg = 0.f;
    const int src = (half << 4);
#pragma unroll
    for (int k = 0; k < 9; k++) {
        int rk = __shfl_sync(0xffffffffu, myrow, src + k);
        uint4 raw = __ldg((const uint4 *)(g_hc16 + (size_t)rk * 128) + hl);
        __half2 p0 = *reinterpret_cast<__half2 *>(&raw.x);
        __half2 p1 = *reinterpret_cast<__half2 *>(&raw.y);
        __half2 p2 = *reinterpret_cast<__half2 *>(&raw.z);
        __half2 p3 = *reinterpret_cast<__half2 *>(&raw.w);
        acc[0] += __low2float(p0); acc[1] += __high2float(p0);
        acc[2] += __low2float(p1); acc[3] += __high2float(p1);
        acc[4] += __low2float(p2); acc[5] += __high2float(p2);
        acc[6] += __low2float(p3); acc[7] += __high2float(p3);
        if (hl < 3 && rk < FC) simg += img[rk * 3 + hl];
    }
    const float inv9 = 1.0f / 9.0f;
    float noise = nc0[face] * ns0[0];
    int c = hl * 8;
    float4 b0v = *(const float4 *)&bias0[c];
    float4 b1v = *(const float4 *)&bias0[c + 4];
    ushort4 h0, h1;
    h0.x = __half_as_ushort(__float2half_rn(actf(acc[0] * inv9 + noise, b0v.x)));
    h0.y = __half_as_ushort(__float2half_rn(actf(acc[1] * inv9 + noise, b0v.y)));
    h0.z = __half_as_ushort(__float2half_rn(actf(acc[2] * inv9 + noise, b0v.z)));
    h0.w = __half_as_ushort(__float2half_rn(actf(acc[3] * inv9 + noise, b0v.w)));
    h1.x = __half_as_ushort(__float2half_rn(actf(acc[4] * inv9 + noise, b1v.x)));
    h1.y = __half_as_ushort(__float2half_rn(actf(acc[5] * inv9 + noise, b1v.y)));
    h1.z = __half_as_ushort(__float2half_rn(actf(acc[6] * inv9 + noise, b1v.z)));
    h1.w = __half_as_ushort(__float2half_rn(actf(acc[7] * inv9 + noise, b1v.w)));
    uint4 packed;
    packed.x = *reinterpret_cast<u32 *>(&h0.x);
    packed.y = *reinterpret_cast<u32 *>(&h0.z);
    packed.z = *reinterpret_cast<u32 *>(&h1.x);
    packed.w = *reinterpret_cast<u32 *>(&h1.z);
    *(uint4 *)&g_h1s[(size_t)face * 128 + c] = packed;

    if (hl < 3) g_imgpart[(size_t)face * 3 + hl] = simg * inv9;
}

// ----------------------------------------------------------------------------
// toRGB
// ----------------------------------------------------------------------------
__global__ void __launch_bounds__(256) torgb_kernel(const void *__restrict__ fn1,
                                                    const float *__restrict__ brgb,
                                                    float *__restrict__ dout) {
    const float *hout = dout;
    float *imgout = dout + (size_t)FFINE * 96;
    const int warp = threadIdx.x >> 5, lane = threadIdx.x & 31;
    const int face = blockIdx.x * 8 + warp;
    int idx = rdidx(fn1, (size_t)face * 9, g_is64);
    float x0 = 0.f, x1 = 0.f, x2 = 0.f;
    if (idx < FFINE) {
        const float *hr = hout + (size_t)idx * 96;
        x0 = hr[lane]; x1 = hr[lane + 32]; x2 = hr[lane + 64];
    }
#pragma unroll
    for (int o = 0; o < 3; o++) {
        float p = x0 * g_wrgbs[o * 96 + lane] + x1 * g_wrgbs[o * 96 + lane + 32] +
                  x2 * g_wrgbs[o * 96 + lane + 64];
#pragma unroll
        for (int s = 16; s > 0; s >>= 1) p += __shfl_xor_sync(0xffffffffu, p, s);
        if (lane == 0) {
            float y = p + brgb[o];
            y = fminf(256.0f, fmaxf(-256.0f, y));
            imgout[(size_t)face * 3 + o] = g_imgpart[(size_t)face * 3 + o] + y;
        }
    }
}

// ----------------------------------------------------------------------------
// Host launcher
// ----------------------------------------------------------------------------
extern "C" void kernel_launch(void *const *d_in, const int *in_sizes, int n_in,
                              void *d_out, int out_size) {
    int base = n_in - 20;

    const float *x   = (const float *)d_in[0];
    const float *sf  = (const float *)d_in[1];
    const float *img = (const float *)d_in[2];
    const float *ws  = (const float *)d_in[3];
    const void  *fn0 = d_in[4];
    const void  *fn1 = d_in[5];
    const void  *pm  = d_in[6];

    const float *a0w  = (const float *)d_in[base + 0];
    const float *a0b  = (const float *)d_in[base + 1];
    const float *wc0  = (const float *)d_in[base + 2];
    const float *ws0  = (const float *)d_in[base + 3];
    const float *wr0  = (const float *)d_in[base + 4];
    const float *ns0  = (const float *)d_in[base + 5];
    const float *b0   = (const float *)d_in[base + 6];
    const float *nc0  = (const float *)d_in[base + 7];
    const float *a1w  = (const float *)d_in[base + 8];
    const float *a1b  = (const float *)d_in[base + 9];
    const float *wc1  = (const float *)d_in[base + 10];
    const float *ws1  = (const float *)d_in[base + 11];
    const float *wr1  = (const float *)d_in[base + 12];
    const float *ns1  = (const float *)d_in[base + 13];
    const float *b1   = (const float *)d_in[base + 14];
    const float *nc1  = (const float *)d_in[base + 15];
    const float *a2w  = (const float *)d_in[base + 16];
    const float *a2b  = (const float *)d_in[base + 17];
    const float *wrgb = (const float *)d_in[base + 18];
    const float *brgb = (const float *)d_in[base + 19];

    const int SMEM = 4 * 32768 + 3 * 32768;  // 229376 (A ring + 3 B types)
    cudaFuncSetAttribute(convmma_kernel<0>, cudaFuncAttributeMaxDynamicSharedMemorySize, SMEM);
    cudaFuncSetAttribute(convmma_kernel<1>, cudaFuncAttributeMaxDynamicSharedMemorySize, SMEM);

    int sms = 148;
    cudaDeviceGetAttribute(&sms, cudaDevAttrMultiProcessorCount, 0);

    float *out = (float *)d_out;
    prep_styles_kernel<<<88, 128>>>(fn1, ws, a0w, a0b, a1w, a1b, a2w, a2b);     // 0
    prep_wp_kernel<<<224 + FC / 4, 128>>>(wc0, ws0, wr0, wc1, ws1, wr1,
                                          x, sf, wrgb);                         // 1
    convmma_kernel<0><<<128, 512, SMEM>>>(fn0, nc0, ns0, b0, out);              // 2
    upsample_kernel<<<FFINE / 16, 256>>>(fn1, pm, img, nc0, ns0, b0);           // 3 (captured)
    convmma_kernel<1><<<sms, 512, SMEM>>>(fn1, nc1, ns1, b1, out);              // 4

    if (out_size >= (long long)FFINE * (96 + NCOL))
        torgb_kernel<<<FFINE / 8, 256>>>(fn1, brgb, out);                       // 5
}

// round 17
// speedup vs baseline: 1.1465x; 1.0552x over previous
#include <cuda_runtime.h>
#include <cuda_fp16.h>
#include <cstdint>
#include <cstddef>

#define FC 32768
#define FFINE 131072
#define NCOL 3

typedef unsigned short u16;
typedef unsigned int   u32;
typedef unsigned long long u64;

// ----------------------------------------------------------------------------
// Device scratch (allocation-free rule)
// ----------------------------------------------------------------------------
__device__ int g_is64;
__device__ __align__(16) float g_s[352];                    // s0(128) s1(128) s2(96)
__device__ __align__(16) u16   g_W0h[3 * 128 * 128];        // [type][i=k][o=n] fp16
__device__ __align__(16) u16   g_W1h[3 * 128 * 96];
__device__ __align__(16) float g_wrgbs[NCOL * 96];
__device__ __align__(16) u16   g_x0s[(size_t)FC * 128];     // fp16 rows (256B)
__device__ __align__(16) u16   g_h1s[(size_t)FFINE * 128];
__device__ __align__(16) u16   g_hc16[((size_t)FC + 8) * 128];  // conv0 fp16 out (+zero row FC)
__device__ __align__(16) float g_imgpart[(size_t)FFINE * NCOL];

// ----------------------------------------------------------------------------
// Helpers
// ----------------------------------------------------------------------------
__device__ __forceinline__ u32 s2u(const void *p) {
    u32 a;
    asm("{ .reg .u64 t; cvta.to.shared.u64 t, %1; cvt.u32.u64 %0, t; }" : "=r"(a) : "l"(p));
    return a;
}
__device__ __forceinline__ float actf(float v, float b) {
    v += b;
    v = (v > 0.0f) ? v : 0.2f * v;
    v *= 1.41421356237309515f;
    return fminf(256.0f, fmaxf(-256.0f, v));
}
__device__ __forceinline__ int rdidx(const void *fn, size_t i, int is64) {
    return is64 ? (int)((const long long *)fn)[i] : ((const int *)fn)[i];
}
__device__ __forceinline__ void ldmx4(u32 addr, u32 *r) {
    asm volatile("ldmatrix.sync.aligned.m8n8.x4.shared.b16 {%0,%1,%2,%3}, [%4];"
                 : "=r"(r[0]), "=r"(r[1]), "=r"(r[2]), "=r"(r[3]) : "r"(addr));
}
__device__ __forceinline__ void ldmx4t(u32 addr, u32 *r) {
    asm volatile("ldmatrix.sync.aligned.m8n8.x4.trans.shared.b16 {%0,%1,%2,%3}, [%4];"
                 : "=r"(r[0]), "=r"(r[1]), "=r"(r[2]), "=r"(r[3]) : "r"(addr));
}
__device__ __forceinline__ void ldmx2t(u32 addr, u32 *r) {
    asm volatile("ldmatrix.sync.aligned.m8n8.x2.trans.shared.b16 {%0,%1}, [%2];"
                 : "=r"(r[0]), "=r"(r[1]) : "r"(addr));
}
__device__ __forceinline__ void mma16816(float *d, const u32 *a, const u32 *b) {
    asm volatile(
        "mma.sync.aligned.m16n8k16.row.col.f32.f16.f16.f32 "
        "{%0,%1,%2,%3}, {%4,%5,%6,%7}, {%8,%9}, {%0,%1,%2,%3};"
        : "+f"(d[0]), "+f"(d[1]), "+f"(d[2]), "+f"(d[3])
        : "r"(a[0]), "r"(a[1]), "r"(a[2]), "r"(a[3]), "r"(b[0]), "r"(b[1]));
}
__device__ __forceinline__ void cpa16(u32 d, const void *s, u32 sz) {
    asm volatile("cp.async.cg.shared.global [%0], [%1], 16, %2;"
                 :: "r"(d), "l"((u64)__cvta_generic_to_global(s)), "r"(sz) : "memory");
}
#define CPCOMMIT() asm volatile("cp.async.commit_group;" ::: "memory")
#define CPWAIT2()  asm volatile("cp.async.wait_group 2;" ::: "memory")

// ----------------------------------------------------------------------------
// Prep 1: styles, one warp per output row. Block 0/thread 0 also detects the
// index dtype (int64 values are small non-negative -> high words all zero).
// ----------------------------------------------------------------------------
__global__ void __launch_bounds__(128)
prep_styles_kernel(const void *__restrict__ fn1raw,
                   const float *__restrict__ ws,
                   const float *__restrict__ a0w, const float *__restrict__ a0b,
                   const float *__restrict__ a1w, const float *__restrict__ a1b,
                   const float *__restrict__ a2w, const float *__restrict__ a2b) {
    if (blockIdx.x == 0 && threadIdx.x == 0) {
        const unsigned *u = (const unsigned *)fn1raw;
        int all0 = 1;
        for (int t = 0; t < 64; t++)
            if (u[2 * t + 1] != 0u) { all0 = 0; break; }
        g_is64 = all0;
    }
    const float inv512 = 0.044194173824159216f;
    const float inv96  = 0.10206207261596575f;
    int gw = blockIdx.x * 4 + (threadIdx.x >> 5);
    int lane = threadIdx.x & 31;
    if (gw >= 352) return;
    const float *wrow, *v;
    float bv, post;
    if (gw < 128)      { wrow = a0w + gw * 512;          v = ws;        bv = a0b[gw];        post = 1.f; }
    else if (gw < 256) { wrow = a1w + (gw - 128) * 512;  v = ws + 512;  bv = a1b[gw - 128];  post = 1.f; }
    else               { wrow = a2w + (gw - 256) * 512;  v = ws + 1024; bv = a2b[gw - 256];  post = inv96; }
    float s = 0.f;
#pragma unroll
    for (int t = 0; t < 16; t++) {
        int d = lane + 32 * t;
        s += v[d] * wrow[d];
    }
#pragma unroll
    for (int o = 16; o > 0; o >>= 1) s += __shfl_xor_sync(0xffffffffu, s, o);
    if (lane == 0) g_s[gw] = (s * inv512 + bv) * post;
}

// ----------------------------------------------------------------------------
// Prep 2 (fused): blocks [0,224): demod + fp16 weight tables;
// blocks [224,...): pack conv0 input rows (fp16, 256B rows).
// ----------------------------------------------------------------------------
__global__ void __launch_bounds__(128)
prep_wp_kernel(const float *__restrict__ wc0, const float *__restrict__ ws0,
               const float *__restrict__ wr0,
               const float *__restrict__ wc1, const float *__restrict__ ws1,
               const float *__restrict__ wr1,
               const float *__restrict__ x, const float *__restrict__ sf,
               const float *__restrict__ wrgb) {
    __shared__ float red[4];
    __shared__ float dsh;
    int blk = blockIdx.x, tid = threadIdx.x;
    if (blk < 224) {
        const int isc0 = (blk < 128);
        const int o = isc0 ? blk : blk - 128;
        const int OUTC = isc0 ? 128 : 96;
        const float *pa = isc0 ? wc0 : wc1;
        const float *pb = isc0 ? ws0 : ws1;
        const float *pc = isc0 ? wr0 : wr1;
        u16 *dst = isc0 ? g_W0h : g_W1h;
        const float *sv = isc0 ? g_s : (g_s + 128);
        int i = tid;
        float a = pa[o * 128 + i], b = pb[o * 128 + i], c = pc[o * 128 + i];
        float si = sv[i];
        float part = si * si * (a * a + 4.f * b * b + 4.f * c * c);
#pragma unroll
        for (int off = 16; off > 0; off >>= 1)
            part += __shfl_xor_sync(0xffffffffu, part, off);
        if ((tid & 31) == 0) red[tid >> 5] = part;
        __syncthreads();
        if (tid == 0) dsh = 1.0f / sqrtf(red[0] + red[1] + red[2] + red[3] + 1e-8f);
        __syncthreads();
        float sid = si * dsh;
        dst[((size_t)0 * 128 + i) * OUTC + o] = __half_as_ushort(__float2half_rn(a * sid));
        dst[((size_t)1 * 128 + i) * OUTC + o] = __half_as_ushort(__float2half_rn(b * sid));
        dst[((size_t)2 * 128 + i) * OUTC + o] = __half_as_ushort(__float2half_rn(c * sid));
        if (!isc0 && tid < 3)
            g_wrgbs[tid * 96 + o] = wrgb[tid * 96 + o] * g_s[256 + o];
    } else {
        int face = (blk - 224) * 4 + (tid >> 5);
        int lane = tid & 31, c = lane * 4;
        float4 v;
        if (c < 96) v = __ldg((const float4 *)(x + (size_t)face * 96) + lane);
        else        v = __ldg((const float4 *)(sf + (size_t)face * 32) + (lane - 24));
        ushort4 h;
        h.x = __half_as_ushort(__float2half_rn(v.x));
        h.y = __half_as_ushort(__float2half_rn(v.y));
        h.z = __half_as_ushort(__float2half_rn(v.z));
        h.w = __half_as_ushort(__float2half_rn(v.w));
        *(ushort4 *)&g_x0s[(size_t)face * 128 + c] = h;
    }
}

// ----------------------------------------------------------------------------
// A staging: 128 rows x 256B (16 x 16B chunks), chunk j at r*256 + ((j^(r&7))<<4).
// 512 threads, 4 chunks each. fn read raw (is64-aware).
// ----------------------------------------------------------------------------
__device__ __forceinline__ void stageA_f(u32 Ad, const u16 *tbl, const void *fn,
                                         int fbase, int k, int tid, int NF, int is64) {
    int r = tid >> 2, q = tid & 3;
    int idx = rdidx(fn, (size_t)(fbase + r) * 9 + k, is64);
    u32 sz = (idx < NF) ? 16u : 0u;
    const char *src = (const char *)tbl + (size_t)(idx < NF ? idx : 0) * 256;
    u32 drow = Ad + (u32)r * 256;
    u32 x = (u32)(r & 7) << 4;
#pragma unroll
    for (int j = q * 4; j < q * 4 + 4; j++)
        cpa16(drow + (((u32)j << 4) ^ x), src + j * 16, sz);
}
// B staging (once): 3 types x 128 rows, row stride 256B (conv1 rows padded).
template <int OUTC>
__device__ __forceinline__ void stageB_all(u32 Bs, const u16 *Wg, int tid) {
    constexpr int NCH = OUTC / 8;  // 16B chunks per row
    for (int cid = tid; cid < 3 * 128 * NCH; cid += 512) {
        int type = cid / (128 * NCH);
        int rr = (cid / NCH) % 128;
        int j = cid % NCH;
        u32 dst = Bs + (u32)type * 32768u + (u32)rr * 256u + (((u32)j << 4) ^ ((u32)(rr & 7) << 4));
        const char *src = (const char *)Wg + ((size_t)type * 128 + rr) * OUTC * 2 + j * 16;
        cpa16(dst, src, 16u);
    }
}

// ----------------------------------------------------------------------------
// HMMA face conv + max over 9 positions, 1-pass fp16, interleaved inner loop
// (both m-subtiles in flight; B ldmatrix per k-step — measured-best form).
// 512 threads: 4 m-warps (32 rows) x 4 n-quarters (OUTC/4 cols).
// ----------------------------------------------------------------------------
template <int WHICH>
__global__ void __launch_bounds__(512, 1)
convmma_kernel(const void *__restrict__ fn,
               const float *__restrict__ nc, const float *__restrict__ nsp,
               const float *__restrict__ bias, float *__restrict__ outp) {
    constexpr int OUTC = (WHICH == 0) ? 128 : 96;
    constexpr int NF = (WHICH == 0) ? FC : FFINE;
    constexpr int NT = NF / 128;
    constexpr int NTL = (WHICH == 0) ? 4 : 3;  // n-tiles (8 cols) per warp

    extern __shared__ char sm[];
    const u32 As = s2u(sm);            // 4 x 32KB ring
    const u32 Bs = As + 131072u;       // 3 x 32KB types
    const u16 *tbl = (WHICH == 0) ? g_x0s : g_h1s;
    const u16 *Wg  = (WHICH == 0) ? g_W0h : g_W1h;
    const int is64 = g_is64;

    const int tid = threadIdx.x, lane = tid & 31, w = tid >> 5;
    const int wm = w & 3, wq = w >> 2;
    const int lrow = lane & 15, lsc = lane >> 4;
    const u32 ax = (u32)(lrow & 7) << 4;
    const int nbase = wq * NTL;
    u32 aoff[2];
#pragma unroll
    for (int ms = 0; ms < 2; ms++) aoff[ms] = (u32)(wm * 32 + ms * 16 + lrow) * 256u;
    const float nsv = (WHICH == 1) ? __ldg(nsp) : 0.f;
    float breg[NTL][2];
    if (WHICH == 1) {
#pragma unroll
        for (int n = 0; n < NTL; n++) {
            int o = nbase * 8 + n * 8 + (lane & 3) * 2;
            breg[n][0] = __ldg(&bias[o]);
            breg[n][1] = __ldg(&bias[o + 1]);
        }
    }

    const int bid = blockIdx.x, grid = gridDim.x;
    const int ntile = (NT - bid + grid - 1) / grid;
    const int steps = ntile * 9;

    // prologue: B (all types) + A(0) in group0; A(1) in group1
    stageB_all<OUTC>(Bs, Wg, tid);
    if (steps > 0) stageA_f(As, tbl, fn, bid * 128, 0, tid, NF, is64);
    CPCOMMIT();
    if (steps > 1) stageA_f(As + 32768u, tbl, fn, bid * 128, 1, tid, NF, is64);
    CPCOMMIT();

    float mx[2][NTL][4];

    for (int s = 0; s < steps; s++) {
        const int k = s - (s / 9) * 9;
        // stage A(s+2)
        {
            int u = s + 2;
            if (u < steps) {
                int ut = u / 9;
                stageA_f(As + (u32)(u & 3) * 32768u, tbl, fn,
                         (bid + ut * grid) * 128, u - ut * 9, tid, NF, is64);
            }
        }
        CPCOMMIT();
        CPWAIT2();
        __syncthreads();

        if (k == 0) {
#pragma unroll
            for (int ms = 0; ms < 2; ms++)
#pragma unroll
                for (int n = 0; n < NTL; n++)
#pragma unroll
                    for (int q = 0; q < 4; q++) mx[ms][n][q] = -3.4e38f;
        }

        const u32 Acur = As + (u32)(s & 3) * 32768u;
        const u32 Bt = Bs + (u32)((k == 0) ? 0 : (k < 5 ? 1 : 2)) * 32768u;
        float acc[2][NTL][4];
#pragma unroll
        for (int ms = 0; ms < 2; ms++)
#pragma unroll
            for (int n = 0; n < NTL; n++)
#pragma unroll
                for (int q = 0; q < 4; q++) acc[ms][n][q] = 0.f;

#pragma unroll
        for (int c = 0; c < 8; c++) {
            u32 a[2][4], bf[NTL][2];
#pragma unroll
            for (int ms = 0; ms < 2; ms++)
                ldmx4(Acur + aoff[ms] + (((u32)(2 * c + lsc) << 4) ^ ax), a[ms]);
            const u32 brow = Bt + (u32)(16 * c + lrow) * 256u;
            if (WHICH == 0) {
#pragma unroll
                for (int p = 0; p < 2; p++) {
                    u32 r4[4];
                    ldmx4t(brow + (((u32)(nbase + 2 * p + lsc) << 4) ^ ax), r4);
                    bf[2 * p][0] = r4[0]; bf[2 * p][1] = r4[1];
                    bf[2 * p + 1][0] = r4[2]; bf[2 * p + 1][1] = r4[3];
                }
            } else {
                u32 r4[4];
                ldmx4t(brow + (((u32)(nbase + lsc) << 4) ^ ax), r4);
                bf[0][0] = r4[0]; bf[0][1] = r4[1];
                bf[1][0] = r4[2]; bf[1][1] = r4[3];
                u32 r2[2];
                ldmx2t(brow + (((u32)(nbase + 2) << 4) ^ ax), r2);
                bf[2][0] = r2[0]; bf[2][1] = r2[1];
            }
#pragma unroll
            for (int ms = 0; ms < 2; ms++)
#pragma unroll
                for (int n = 0; n < NTL; n++) mma16816(acc[ms][n], a[ms], bf[n]);
        }
#pragma unroll
        for (int ms = 0; ms < 2; ms++)
#pragma unroll
            for (int n = 0; n < NTL; n++)
#pragma unroll
                for (int q = 0; q < 4; q++)
                    mx[ms][n][q] = fmaxf(mx[ms][n][q], acc[ms][n][q]);

        if (k == 8) {
            const int fbase = (bid + (s / 9) * grid) * 128;
#pragma unroll
            for (int ms = 0; ms < 2; ms++) {
                int f0 = fbase + wm * 32 + ms * 16 + (lane >> 2);
                if (WHICH == 0) {
#pragma unroll
                    for (int n = 0; n < NTL; n++) {
                        int o = nbase * 8 + n * 8 + (lane & 3) * 2;
                        __half2 h01 = __floats2half2_rn(mx[ms][n][0], mx[ms][n][1]);
                        __half2 h23 = __floats2half2_rn(mx[ms][n][2], mx[ms][n][3]);
                        *(u32 *)&g_hc16[(size_t)f0 * 128 + o] = *reinterpret_cast<u32 *>(&h01);
                        *(u32 *)&g_hc16[(size_t)(f0 + 8) * 128 + o] = *reinterpret_cast<u32 *>(&h23);
                    }
                } else {
                    float nz0 = __ldg(&nc[f0]) * nsv;
                    float nz1 = __ldg(&nc[f0 + 8]) * nsv;
#pragma unroll
                    for (int n = 0; n < NTL; n++) {
                        int o = nbase * 8 + n * 8 + (lane & 3) * 2;
                        *(float2 *)&outp[(size_t)f0 * 96 + o] =
                            make_float2(actf(mx[ms][n][0] + nz0, breg[n][0]),
                                        actf(mx[ms][n][1] + nz0, breg[n][1]));
                        *(float2 *)&outp[(size_t)(f0 + 8) * 96 + o] =
                            make_float2(actf(mx[ms][n][2] + nz1, breg[n][0]),
                                        actf(mx[ms][n][3] + nz1, breg[n][1]));
                    }
                }
            }
        }
    }
}

// ----------------------------------------------------------------------------
// Smooth upsample: 2 faces per warp (16 lanes x 8 channels, uint4 loads),
// fp32 accumulation, branch-free gather via zero row at index FC.
// launch_bounds(256, 8): cap regs at 32 -> full occupancy.
// ----------------------------------------------------------------------------
__global__ void __launch_bounds__(256, 8)
upsample_kernel(const void *__restrict__ fn1,
                const void *__restrict__ pm,
                const float *__restrict__ img,
                const float *__restrict__ nc0,
                const float *__restrict__ ns0,
                const float *__restrict__ bias0) {
    const int warp = threadIdx.x >> 5, lane = threadIdx.x & 31;
    const int half = lane >> 4, hl = lane & 15;
    const int face = blockIdx.x * 16 + warp * 2 + half;
    const int is64 = g_is64;
    int myrow = FC;  // zero row
    if (hl < 9) {
        int v = rdidx(fn1, (size_t)face * 9 + hl, is64);
        if (v < FFINE) myrow = rdidx(pm, v, is64);
    }
    float acc[8];
#pragma unroll
    for (int j = 0; j < 8; j++) acc[j] = 0.f;
    float simg = 0.f;
    const int src = (half << 4);
#pragma unroll
    for (int k = 0; k < 9; k++) {
        int rk = __shfl_sync(0xffffffffu, myrow, src + k);
        uint4 raw = __ldg((const uint4 *)(g_hc16 + (size_t)rk * 128) + hl);
        __half2 p0 = *reinterpret_cast<__half2 *>(&raw.x);
        __half2 p1 = *reinterpret_cast<__half2 *>(&raw.y);
        __half2 p2 = *reinterpret_cast<__half2 *>(&raw.z);
        __half2 p3 = *reinterpret_cast<__half2 *>(&raw.w);
        acc[0] += __low2float(p0); acc[1] += __high2float(p0);
        acc[2] += __low2float(p1); acc[3] += __high2float(p1);
        acc[4] += __low2float(p2); acc[5] += __high2float(p2);
        acc[6] += __low2float(p3); acc[7] += __high2float(p3);
        if (hl < 3 && rk < FC) simg += img[rk * 3 + hl];
    }
    const float inv9 = 1.0f / 9.0f;
    float noise = nc0[face] * ns0[0];
    int c = hl * 8;
    float4 b0v = *(const float4 *)&bias0[c];
    float4 b1v = *(const float4 *)&bias0[c + 4];
    ushort4 h0, h1;
    h0.x = __half_as_ushort(__float2half_rn(actf(acc[0] * inv9 + noise, b0v.x)));
    h0.y = __half_as_ushort(__float2half_rn(actf(acc[1] * inv9 + noise, b0v.y)));
    h0.z = __half_as_ushort(__float2half_rn(actf(acc[2] * inv9 + noise, b0v.z)));
    h0.w = __half_as_ushort(__float2half_rn(actf(acc[3] * inv9 + noise, b0v.w)));
    h1.x = __half_as_ushort(__float2half_rn(actf(acc[4] * inv9 + noise, b1v.x)));
    h1.y = __half_as_ushort(__float2half_rn(actf(acc[5] * inv9 + noise, b1v.y)));
    h1.z = __half_as_ushort(__float2half_rn(actf(acc[6] * inv9 + noise, b1v.z)));
    h1.w = __half_as_ushort(__float2half_rn(actf(acc[7] * inv9 + noise, b1v.w)));
    uint4 packed;
    packed.x = *reinterpret_cast<u32 *>(&h0.x);
    packed.y = *reinterpret_cast<u32 *>(&h0.z);
    packed.z = *reinterpret_cast<u32 *>(&h1.x);
    packed.w = *reinterpret_cast<u32 *>(&h1.z);
    *(uint4 *)&g_h1s[(size_t)face * 128 + c] = packed;

    if (hl < 3) g_imgpart[(size_t)face * 3 + hl] = simg * inv9;
}

// ----------------------------------------------------------------------------
// toRGB: 2 faces per warp, 16 lanes x 6 channels; 4-shfl reductions (xor
// offsets 1..8 stay within the 16-lane half).
// ----------------------------------------------------------------------------
__global__ void __launch_bounds__(256) torgb_kernel(const void *__restrict__ fn1,
                                                    const float *__restrict__ brgb,
                                                    float *__restrict__ dout) {
    const float *hout = dout;
    float *imgout = dout + (size_t)FFINE * 96;
    const int warp = threadIdx.x >> 5, lane = threadIdx.x & 31;
    const int half = lane >> 4, hl = lane & 15;
    const int face = blockIdx.x * 16 + warp * 2 + half;
    int idx = rdidx(fn1, (size_t)face * 9, g_is64);
    float xv[6];
    if (idx < FFINE) {
        const float *hr = hout + (size_t)idx * 96;
#pragma unroll
        for (int j = 0; j < 6; j++) xv[j] = hr[hl + 16 * j];
    } else {
#pragma unroll
        for (int j = 0; j < 6; j++) xv[j] = 0.f;
    }
#pragma unroll
    for (int o = 0; o < 3; o++) {
        float p = 0.f;
#pragma unroll
        for (int j = 0; j < 6; j++) p += xv[j] * g_wrgbs[o * 96 + hl + 16 * j];
#pragma unroll
        for (int s = 8; s > 0; s >>= 1) p += __shfl_xor_sync(0xffffffffu, p, s);
        if (hl == 0) {
            float y = p + brgb[o];
            y = fminf(256.0f, fmaxf(-256.0f, y));
            imgout[(size_t)face * 3 + o] = g_imgpart[(size_t)face * 3 + o] + y;
        }
    }
}

// ----------------------------------------------------------------------------
// Host launcher
// ----------------------------------------------------------------------------
extern "C" void kernel_launch(void *const *d_in, const int *in_sizes, int n_in,
                              void *d_out, int out_size) {
    int base = n_in - 20;

    const float *x   = (const float *)d_in[0];
    const float *sf  = (const float *)d_in[1];
    const float *img = (const float *)d_in[2];
    const float *ws  = (const float *)d_in[3];
    const void  *fn0 = d_in[4];
    const void  *fn1 = d_in[5];
    const void  *pm  = d_in[6];

    const float *a0w  = (const float *)d_in[base + 0];
    const float *a0b  = (const float *)d_in[base + 1];
    const float *wc0  = (const float *)d_in[base + 2];
    const float *ws0  = (const float *)d_in[base + 3];
    const float *wr0  = (const float *)d_in[base + 4];
    const float *ns0  = (const float *)d_in[base + 5];
    const float *b0   = (const float *)d_in[base + 6];
    const float *nc0  = (const float *)d_in[base + 7];
    const float *a1w  = (const float *)d_in[base + 8];
    const float *a1b  = (const float *)d_in[base + 9];
    const float *wc1  = (const float *)d_in[base + 10];
    const float *ws1  = (const float *)d_in[base + 11];
    const float *wr1  = (const float *)d_in[base + 12];
    const float *ns1  = (const float *)d_in[base + 13];
    const float *b1   = (const float *)d_in[base + 14];
    const float *nc1  = (const float *)d_in[base + 15];
    const float *a2w  = (const float *)d_in[base + 16];
    const float *a2b  = (const float *)d_in[base + 17];
    const float *wrgb = (const float *)d_in[base + 18];
    const float *brgb = (const float *)d_in[base + 19];

    const int SMEM = 4 * 32768 + 3 * 32768;  // 229376 (A ring + 3 B types)
    cudaFuncSetAttribute(convmma_kernel<0>, cudaFuncAttributeMaxDynamicSharedMemorySize, SMEM);
    cudaFuncSetAttribute(convmma_kernel<1>, cudaFuncAttributeMaxDynamicSharedMemorySize, SMEM);

    int sms = 148;
    cudaDeviceGetAttribute(&sms, cudaDevAttrMultiProcessorCount, 0);

    float *out = (float *)d_out;
    prep_styles_kernel<<<88, 128>>>(fn1, ws, a0w, a0b, a1w, a1b, a2w, a2b);     // 0
    prep_wp_kernel<<<224 + FC / 4, 128>>>(wc0, ws0, wr0, wc1, ws1, wr1,
                                          x, sf, wrgb);                         // 1
    convmma_kernel<0><<<128, 512, SMEM>>>(fn0, nc0, ns0, b0, out);              // 2
    upsample_kernel<<<FFINE / 16, 256>>>(fn1, pm, img, nc0, ns0, b0);           // 3 (captured)
    convmma_kernel<1><<<sms, 512, SMEM>>>(fn1, nc1, ns1, b1, out);              // 4

    if (out_size >= (long long)FFINE * (96 + NCOL))
        torgb_kernel<<<FFINE / 16, 256>>>(fn1, brgb, out);                      // 5
}